// round 1
// baseline (speedup 1.0000x reference)
#include <cuda_runtime.h>

// ---------------------------------------------------------------------------
// Problem: 2x DGL SAGEConv(pool) on N=1M nodes / E=16M edges, then fused
// command product + 10->32->32->32->1 sigmoid MLP at L=131072 leaf nodes.
//
// Scratch: padded-to-8 rows so each node row is one aligned 32B sector.
// ---------------------------------------------------------------------------

#define NMAX 1000000

__device__ float g_m  [NMAX * 8];   // relu(fc_pool(h)) per node (layer 1, then layer 2)
__device__ float g_agg[NMAX * 8];   // segment-max accumulator (nonneg floats as int bits)
__device__ float g_h1 [NMAX * 8];   // sigmoid output of layer 1

__device__ __forceinline__ float sigm(float x) { return 1.0f / (1.0f + __expf(-x)); }

// ---------------------------------------------------------------------------
// K0: m1 = relu(x @ p1_W + p1_b); agg = 0
// ---------------------------------------------------------------------------
__global__ void k_pool1(const float* __restrict__ x,
                        const float* __restrict__ Wp, const float* __restrict__ bp,
                        int N) {
    int i = blockIdx.x * blockDim.x + threadIdx.x;
    if (i >= N) return;
    float v[5];
#pragma unroll
    for (int k = 0; k < 5; k++) v[k] = x[(size_t)i * 5 + k];
    float mm[5];
#pragma unroll
    for (int f = 0; f < 5; f++) {
        float s = bp[f];
#pragma unroll
        for (int k = 0; k < 5; k++) s += v[k] * Wp[k * 5 + f];
        mm[f] = fmaxf(s, 0.0f);
    }
    float4* mr = (float4*)(g_m + (size_t)i * 8);
    mr[0] = make_float4(mm[0], mm[1], mm[2], mm[3]);
    mr[1] = make_float4(mm[4], 0.f, 0.f, 0.f);
    float4* ar = (float4*)(g_agg + (size_t)i * 8);
    ar[0] = make_float4(0.f, 0.f, 0.f, 0.f);
    ar[1] = make_float4(0.f, 0.f, 0.f, 0.f);
}

// ---------------------------------------------------------------------------
// Edge pass: agg[dst] = max(agg[dst], m[src]) elementwise.
// m >= 0 (relu), agg init 0  =>  signed-int atomicMax on float bits is exact.
// Unused return -> RED (no-return reduction) in SASS.
// ---------------------------------------------------------------------------
__global__ void k_edge(const int* __restrict__ src, const int* __restrict__ dst, int E) {
    int e = blockIdx.x * blockDim.x + threadIdx.x;
    if (e >= E) return;
    int s = __ldcs(src + e);
    int d = __ldcs(dst + e);
    const float4* mr = (const float4*)(g_m + (size_t)s * 8);
    float4 a = mr[0];
    float4 b = mr[1];
    int* ag = (int*)(g_agg + (size_t)d * 8);
    atomicMax(ag + 0, __float_as_int(a.x));
    atomicMax(ag + 1, __float_as_int(a.y));
    atomicMax(ag + 2, __float_as_int(a.z));
    atomicMax(ag + 3, __float_as_int(a.w));
    atomicMax(ag + 4, __float_as_int(b.x));
}

// ---------------------------------------------------------------------------
// K2: h1 = sigmoid(x @ s1 + agg1 @ n1 + b1); m2 = relu(h1 @ p2 + p2_b); agg = 0
// ---------------------------------------------------------------------------
__global__ void k_mid(const float* __restrict__ x,
                      const float* __restrict__ Ws, const float* __restrict__ Wn,
                      const float* __restrict__ b1,
                      const float* __restrict__ Wp2, const float* __restrict__ bp2,
                      int N) {
    int i = blockIdx.x * blockDim.x + threadIdx.x;
    if (i >= N) return;
    float v[5];
#pragma unroll
    for (int k = 0; k < 5; k++) v[k] = x[(size_t)i * 5 + k];
    float4 a0 = *(const float4*)(g_agg + (size_t)i * 8);
    float4 a1 = *(const float4*)(g_agg + (size_t)i * 8 + 4);
    float ag[5] = {a0.x, a0.y, a0.z, a0.w, a1.x};

    float h1[5];
#pragma unroll
    for (int f = 0; f < 5; f++) {
        float s = b1[f];
#pragma unroll
        for (int k = 0; k < 5; k++) s += v[k] * Ws[k * 5 + f] + ag[k] * Wn[k * 5 + f];
        h1[f] = sigm(s);
    }
    float m2[5];
#pragma unroll
    for (int f = 0; f < 5; f++) {
        float s = bp2[f];
#pragma unroll
        for (int k = 0; k < 5; k++) s += h1[k] * Wp2[k * 5 + f];
        m2[f] = fmaxf(s, 0.0f);
    }
    float4* hr = (float4*)(g_h1 + (size_t)i * 8);
    hr[0] = make_float4(h1[0], h1[1], h1[2], h1[3]);
    hr[1] = make_float4(h1[4], 0.f, 0.f, 0.f);
    float4* mr = (float4*)(g_m + (size_t)i * 8);
    mr[0] = make_float4(m2[0], m2[1], m2[2], m2[3]);
    mr[1] = make_float4(m2[4], 0.f, 0.f, 0.f);
    float4* ar = (float4*)(g_agg + (size_t)i * 8);
    ar[0] = make_float4(0.f, 0.f, 0.f, 0.f);
    ar[1] = make_float4(0.f, 0.f, 0.f, 0.f);
}

// ---------------------------------------------------------------------------
// K4: fused leaf output.  Only leaf nodes need h2:
//   h2 = h1 @ s2 + agg2 @ n2 + b2            (10)
//   prod = h2 * (command @ cmd_W + cmd_b)    (10)
//   out  = sigmoid MLP 10->32->32->32->1
// All weights staged in shared memory (uniform broadcast LDS).
// ---------------------------------------------------------------------------
__global__ void k_leaf(const int* __restrict__ leaf, const float* __restrict__ cmd,
                       const float* __restrict__ s2, const float* __restrict__ n2,
                       const float* __restrict__ b2,
                       const float* __restrict__ cmdW, const float* __restrict__ cmdb,
                       const float* __restrict__ o1W, const float* __restrict__ o1b,
                       const float* __restrict__ o2W, const float* __restrict__ o2b,
                       const float* __restrict__ o3W, const float* __restrict__ o3b,
                       const float* __restrict__ o4W, const float* __restrict__ o4b,
                       float* __restrict__ out, int L) {
    __shared__ float shS2[50], shN2[50], shB2[10], shENC[10];
    __shared__ float shO1W[320], shO1B[32];
    __shared__ float shO2W[1024], shO2B[32];
    __shared__ float shO3W[1024], shO3B[32];
    __shared__ float shO4W[32];
    __shared__ float shO4B;

    int t = threadIdx.x;
    for (int j = t; j < 50;   j += blockDim.x) shS2[j]  = s2[j];
    for (int j = t; j < 50;   j += blockDim.x) shN2[j]  = n2[j];
    for (int j = t; j < 10;   j += blockDim.x) shB2[j]  = b2[j];
    for (int j = t; j < 320;  j += blockDim.x) shO1W[j] = o1W[j];
    for (int j = t; j < 32;   j += blockDim.x) shO1B[j] = o1b[j];
    for (int j = t; j < 1024; j += blockDim.x) shO2W[j] = o2W[j];
    for (int j = t; j < 32;   j += blockDim.x) shO2B[j] = o2b[j];
    for (int j = t; j < 1024; j += blockDim.x) shO3W[j] = o3W[j];
    for (int j = t; j < 32;   j += blockDim.x) shO3B[j] = o3b[j];
    for (int j = t; j < 32;   j += blockDim.x) shO4W[j] = o4W[j];
    if (t < 10) shENC[t] = cmd[0] * cmdW[t] + cmd[1] * cmdW[10 + t] + cmdb[t];
    if (t == 0) shO4B = o4b[0];
    __syncthreads();

    int l = blockIdx.x * blockDim.x + t;
    if (l >= L) return;

    int n = leaf[l];
    float4 h0 = *(const float4*)(g_h1 + (size_t)n * 8);
    float4 h1v = *(const float4*)(g_h1 + (size_t)n * 8 + 4);
    float4 a0 = *(const float4*)(g_agg + (size_t)n * 8);
    float4 a1 = *(const float4*)(g_agg + (size_t)n * 8 + 4);
    float hv[5] = {h0.x, h0.y, h0.z, h0.w, h1v.x};
    float av[5] = {a0.x, a0.y, a0.z, a0.w, a1.x};

    float p[10];
#pragma unroll
    for (int j = 0; j < 10; j++) {
        float s = shB2[j];
#pragma unroll
        for (int k = 0; k < 5; k++) s += hv[k] * shS2[k * 10 + j] + av[k] * shN2[k * 10 + j];
        p[j] = s * shENC[j];
    }

    float z1[32];
#pragma unroll
    for (int j = 0; j < 32; j++) {
        float s = shO1B[j];
#pragma unroll
        for (int k = 0; k < 10; k++) s += p[k] * shO1W[k * 32 + j];
        z1[j] = sigm(s);
    }
    float z2[32];
#pragma unroll
    for (int j = 0; j < 32; j++) {
        float s = shO2B[j];
#pragma unroll
        for (int k = 0; k < 32; k++) s += z1[k] * shO2W[k * 32 + j];
        z2[j] = sigm(s);
    }
    float z3[32];
#pragma unroll
    for (int j = 0; j < 32; j++) {
        float s = shO3B[j];
#pragma unroll
        for (int k = 0; k < 32; k++) s += z2[k] * shO3W[k * 32 + j];
        z3[j] = sigm(s);
    }
    float s = shO4B;
#pragma unroll
    for (int k = 0; k < 32; k++) s += z3[k] * shO4W[k];
    out[l] = sigm(s);
}

// ---------------------------------------------------------------------------
// launch
// ---------------------------------------------------------------------------
extern "C" void kernel_launch(void* const* d_in, const int* in_sizes, int n_in,
                              void* d_out, int out_size) {
    const float* x    = (const float*)d_in[0];
    const int*   src  = (const int*)  d_in[1];
    const int*   dst  = (const int*)  d_in[2];
    const int*   leaf = (const int*)  d_in[3];
    const float* cmd  = (const float*)d_in[4];
    const float* p1W  = (const float*)d_in[5];
    const float* p1b  = (const float*)d_in[6];
    const float* s1W  = (const float*)d_in[7];
    const float* n1W  = (const float*)d_in[8];
    const float* b1   = (const float*)d_in[9];
    const float* p2W  = (const float*)d_in[10];
    const float* p2b  = (const float*)d_in[11];
    const float* s2W  = (const float*)d_in[12];
    const float* n2W  = (const float*)d_in[13];
    const float* b2   = (const float*)d_in[14];
    const float* cmdW = (const float*)d_in[15];
    const float* cmdb = (const float*)d_in[16];
    const float* o1W  = (const float*)d_in[17];
    const float* o1b  = (const float*)d_in[18];
    const float* o2W  = (const float*)d_in[19];
    const float* o2b  = (const float*)d_in[20];
    const float* o3W  = (const float*)d_in[21];
    const float* o3b  = (const float*)d_in[22];
    const float* o4W  = (const float*)d_in[23];
    const float* o4b  = (const float*)d_in[24];
    float* out = (float*)d_out;

    int N = in_sizes[0] / 5;
    int E = in_sizes[1];
    int L = in_sizes[3];

    const int BT = 256;
    int nb = (N + BT - 1) / BT;
    int eb = (E + BT - 1) / BT;
    int lb = (L + BT - 1) / BT;

    // Layer 1
    k_pool1<<<nb, BT>>>(x, p1W, p1b, N);
    k_edge <<<eb, BT>>>(src, dst, E);
    // Layer 1 combine + layer 2 pool-fc + agg reset
    k_mid  <<<nb, BT>>>(x, s1W, n1W, b1, p2W, p2b, N);
    // Layer 2 aggregation
    k_edge <<<eb, BT>>>(src, dst, E);
    // Fused leaf-only layer-2 combine + command + MLP
    k_leaf <<<lb, BT>>>(leaf, cmd, s2W, n2W, b2, cmdW, cmdb,
                        o1W, o1b, o2W, o2b, o3W, o3b, o4W, o4b, out, L);
}

// round 3
// speedup vs baseline: 1.6965x; 1.6965x over previous
#include <cuda_runtime.h>

// ---------------------------------------------------------------------------
// 2x SAGEConv(pool) N=1M, E=16M + leaf MLP (L=131072).
// Strategy: build dst-CSR once per launch (counting sort), then both "edge
// passes" are atomic-free register max-gathers. Layer-2 aggregation runs ONLY
// at leaf nodes (h2 is consumed nowhere else).
// ---------------------------------------------------------------------------

#define NMAX 1000000
#define EMAX 16000000
#define SCAN_CHUNK 4096   // 1024 threads * 4 items

__device__ float g_m1 [NMAX * 8];    // relu(fc_pool1(x)) rows, 32B-aligned
__device__ float g_m2 [NMAX * 8];    // relu(fc_pool2(h1)) rows
__device__ float g_h1 [NMAX * 8];    // sigmoid layer-1 output rows
__device__ int   g_deg [NMAX];
__device__ int   g_row [NMAX];       // CSR row starts (exclusive prefix of deg)
__device__ int   g_cur [NMAX];       // scatter cursors
__device__ int   g_ssrc[EMAX];       // src ids sorted by dst
__device__ int   g_bsum[1024];       // scan block sums

__device__ __forceinline__ float sigm(float x) { return 1.0f / (1.0f + __expf(-x)); }

// Max over one source row (5 floats in one 32B sector).
__device__ __forceinline__ void row_max(const float* __restrict__ base, int s,
                                        float& m0, float& m1, float& m2,
                                        float& m3, float& m4) {
    float4 a = __ldg((const float4*)(base + (size_t)s * 8));
    float e4 = __ldg(base + (size_t)s * 8 + 4);
    m0 = fmaxf(m0, a.x); m1 = fmaxf(m1, a.y);
    m2 = fmaxf(m2, a.z); m3 = fmaxf(m3, a.w);
    m4 = fmaxf(m4, e4);
}

// --------------------------- K0: pool1 + zero deg ---------------------------
__global__ void k_pool1(const float* __restrict__ x,
                        const float* __restrict__ Wp, const float* __restrict__ bp,
                        int N) {
    int i = blockIdx.x * blockDim.x + threadIdx.x;
    if (i >= N) return;
    float v[5];
#pragma unroll
    for (int k = 0; k < 5; k++) v[k] = x[(size_t)i * 5 + k];
    float mm[5];
#pragma unroll
    for (int f = 0; f < 5; f++) {
        float s = bp[f];
#pragma unroll
        for (int k = 0; k < 5; k++) s += v[k] * Wp[k * 5 + f];
        mm[f] = fmaxf(s, 0.0f);
    }
    float4* mr = (float4*)(g_m1 + (size_t)i * 8);
    mr[0] = make_float4(mm[0], mm[1], mm[2], mm[3]);
    mr[1] = make_float4(mm[4], 0.f, 0.f, 0.f);
    g_deg[i] = 0;
}

// --------------------------- K1: degree histogram ---------------------------
__global__ void k_hist(const int* __restrict__ dst, int E) {
    int e = blockIdx.x * blockDim.x + threadIdx.x;
    if (e >= E) return;
    atomicAdd(g_deg + __ldcs(dst + e), 1);
}

// --------------------------- K2: per-chunk scan -----------------------------
__global__ void k_scan_partial(int N) {
    __shared__ int warpSums[32];
    int lane = threadIdx.x & 31, wid = threadIdx.x >> 5;
    int base = blockIdx.x * SCAN_CHUNK + threadIdx.x * 4;
    int v[4];
#pragma unroll
    for (int k = 0; k < 4; k++) {
        int idx = base + k;
        v[k] = (idx < N) ? g_deg[idx] : 0;
    }
    int t = v[0] + v[1] + v[2] + v[3];
    int s = t;
#pragma unroll
    for (int o = 1; o < 32; o <<= 1) {
        int u = __shfl_up_sync(~0u, s, o);
        if (lane >= o) s += u;
    }
    if (lane == 31) warpSums[wid] = s;
    __syncthreads();
    if (wid == 0) {
        int ws = warpSums[lane];
#pragma unroll
        for (int o = 1; o < 32; o <<= 1) {
            int u = __shfl_up_sync(~0u, ws, o);
            if (lane >= o) ws += u;
        }
        warpSums[lane] = ws;
    }
    __syncthreads();
    int warpOff = (wid > 0) ? warpSums[wid - 1] : 0;
    int run = warpOff + s - t;   // exclusive prefix of this thread within chunk
#pragma unroll
    for (int k = 0; k < 4; k++) {
        int idx = base + k;
        if (idx < N) g_row[idx] = run;
        run += v[k];
    }
    if (threadIdx.x == 0) g_bsum[blockIdx.x] = warpSums[31];
}

// --------------------------- K3: scan the chunk sums ------------------------
__global__ void k_scan_sums(int NB) {
    __shared__ int sm[1024];
    int t = threadIdx.x;
    int v = (t < NB) ? g_bsum[t] : 0;
    sm[t] = v;
    __syncthreads();
    for (int o = 1; o < 1024; o <<= 1) {
        int u = (t >= o) ? sm[t - o] : 0;
        __syncthreads();
        sm[t] += u;
        __syncthreads();
    }
    if (t < NB) g_bsum[t] = sm[t] - v;   // exclusive
}

// --------------------------- K4: add offsets, init cursors ------------------
__global__ void k_scan_add(int N) {
    int i = blockIdx.x * blockDim.x + threadIdx.x;
    if (i >= N) return;
    int r = g_row[i] + g_bsum[i / SCAN_CHUNK];
    g_row[i] = r;
    g_cur[i] = r;
}

// --------------------------- K5: scatter (sort by dst) ----------------------
__global__ void k_scatter(const int* __restrict__ src, const int* __restrict__ dst, int E) {
    int e = blockIdx.x * blockDim.x + threadIdx.x;
    if (e >= E) return;
    int s = __ldcs(src + e);
    int d = __ldcs(dst + e);
    int p = atomicAdd(g_cur + d, 1);
    g_ssrc[p] = s;
}

// ---- K6: per-node agg1 (register max over CSR segment) + h1 + m2 -----------
__global__ void k_gather_mid(const float* __restrict__ x,
                             const float* __restrict__ Ws, const float* __restrict__ Wn,
                             const float* __restrict__ b1,
                             const float* __restrict__ Wp2, const float* __restrict__ bp2,
                             int N) {
    int i = blockIdx.x * blockDim.x + threadIdx.x;
    if (i >= N) return;
    int start = g_row[i];
    int d = g_deg[i];
    // Two independent accumulator sets -> 2x memory-level parallelism.
    float a0 = 0.f, a1 = 0.f, a2 = 0.f, a3 = 0.f, a4 = 0.f;
    float c0 = 0.f, c1 = 0.f, c2 = 0.f, c3 = 0.f, c4 = 0.f;
    int j = 0;
    for (; j + 1 < d; j += 2) {
        int s0 = __ldcs(g_ssrc + start + j);
        int s1 = __ldcs(g_ssrc + start + j + 1);
        row_max(g_m1, s0, a0, a1, a2, a3, a4);
        row_max(g_m1, s1, c0, c1, c2, c3, c4);
    }
    if (j < d) {
        int s0 = __ldcs(g_ssrc + start + j);
        row_max(g_m1, s0, a0, a1, a2, a3, a4);
    }
    float ag[5] = {fmaxf(a0, c0), fmaxf(a1, c1), fmaxf(a2, c2),
                   fmaxf(a3, c3), fmaxf(a4, c4)};
    float v[5];
#pragma unroll
    for (int k = 0; k < 5; k++) v[k] = x[(size_t)i * 5 + k];
    float h1[5];
#pragma unroll
    for (int f = 0; f < 5; f++) {
        float s = b1[f];
#pragma unroll
        for (int k = 0; k < 5; k++) s += v[k] * Ws[k * 5 + f] + ag[k] * Wn[k * 5 + f];
        h1[f] = sigm(s);
    }
    float m2[5];
#pragma unroll
    for (int f = 0; f < 5; f++) {
        float s = bp2[f];
#pragma unroll
        for (int k = 0; k < 5; k++) s += h1[k] * Wp2[k * 5 + f];
        m2[f] = fmaxf(s, 0.0f);
    }
    float4* hr = (float4*)(g_h1 + (size_t)i * 8);
    hr[0] = make_float4(h1[0], h1[1], h1[2], h1[3]);
    hr[1] = make_float4(h1[4], 0.f, 0.f, 0.f);
    float4* mr = (float4*)(g_m2 + (size_t)i * 8);
    mr[0] = make_float4(m2[0], m2[1], m2[2], m2[3]);
    mr[1] = make_float4(m2[4], 0.f, 0.f, 0.f);
}

// ---- K7: leaf-only layer-2 aggregation + combine + command + MLP -----------
__global__ void k_leaf(const int* __restrict__ leaf, const float* __restrict__ cmd,
                       const float* __restrict__ s2, const float* __restrict__ n2,
                       const float* __restrict__ b2,
                       const float* __restrict__ cmdW, const float* __restrict__ cmdb,
                       const float* __restrict__ o1W, const float* __restrict__ o1b,
                       const float* __restrict__ o2W, const float* __restrict__ o2b,
                       const float* __restrict__ o3W, const float* __restrict__ o3b,
                       const float* __restrict__ o4W, const float* __restrict__ o4b,
                       float* __restrict__ out, int L) {
    __shared__ float shS2[50], shN2[50], shB2[10], shENC[10];
    __shared__ float shO1W[320], shO1B[32];
    __shared__ float shO2W[1024], shO2B[32];
    __shared__ float shO3W[1024], shO3B[32];
    __shared__ float shO4W[32];
    __shared__ float shO4B;

    int t = threadIdx.x;
    for (int j = t; j < 50;   j += blockDim.x) shS2[j]  = s2[j];
    for (int j = t; j < 50;   j += blockDim.x) shN2[j]  = n2[j];
    for (int j = t; j < 10;   j += blockDim.x) shB2[j]  = b2[j];
    for (int j = t; j < 320;  j += blockDim.x) shO1W[j] = o1W[j];
    for (int j = t; j < 32;   j += blockDim.x) shO1B[j] = o1b[j];
    for (int j = t; j < 1024; j += blockDim.x) shO2W[j] = o2W[j];
    for (int j = t; j < 32;   j += blockDim.x) shO2B[j] = o2b[j];
    for (int j = t; j < 1024; j += blockDim.x) shO3W[j] = o3W[j];
    for (int j = t; j < 32;   j += blockDim.x) shO3B[j] = o3b[j];
    for (int j = t; j < 32;   j += blockDim.x) shO4W[j] = o4W[j];
    if (t < 10) shENC[t] = cmd[0] * cmdW[t] + cmd[1] * cmdW[10 + t] + cmdb[t];
    if (t == 0) shO4B = o4b[0];
    __syncthreads();

    int l = blockIdx.x * blockDim.x + t;
    if (l >= L) return;

    int n = leaf[l];
    // Layer-2 aggregation at this node only
    int start = g_row[n];
    int d = g_deg[n];
    float a0 = 0.f, a1 = 0.f, a2 = 0.f, a3 = 0.f, a4 = 0.f;
    float c0 = 0.f, c1 = 0.f, c2 = 0.f, c3 = 0.f, c4 = 0.f;
    int j = 0;
    for (; j + 1 < d; j += 2) {
        int s0 = __ldg(g_ssrc + start + j);
        int s1 = __ldg(g_ssrc + start + j + 1);
        row_max(g_m2, s0, a0, a1, a2, a3, a4);
        row_max(g_m2, s1, c0, c1, c2, c3, c4);
    }
    if (j < d) {
        int s0 = __ldg(g_ssrc + start + j);
        row_max(g_m2, s0, a0, a1, a2, a3, a4);
    }
    float av[5] = {fmaxf(a0, c0), fmaxf(a1, c1), fmaxf(a2, c2),
                   fmaxf(a3, c3), fmaxf(a4, c4)};
    float4 h0  = *(const float4*)(g_h1 + (size_t)n * 8);
    float  h4  = g_h1[(size_t)n * 8 + 4];
    float hv[5] = {h0.x, h0.y, h0.z, h0.w, h4};

    float p[10];
#pragma unroll
    for (int jj = 0; jj < 10; jj++) {
        float s = shB2[jj];
#pragma unroll
        for (int k = 0; k < 5; k++) s += hv[k] * shS2[k * 10 + jj] + av[k] * shN2[k * 10 + jj];
        p[jj] = s * shENC[jj];
    }

    float z1[32];
#pragma unroll
    for (int jj = 0; jj < 32; jj++) {
        float s = shO1B[jj];
#pragma unroll
        for (int k = 0; k < 10; k++) s += p[k] * shO1W[k * 32 + jj];
        z1[jj] = sigm(s);
    }
    float z2[32];
#pragma unroll
    for (int jj = 0; jj < 32; jj++) {
        float s = shO2B[jj];
#pragma unroll
        for (int k = 0; k < 32; k++) s += z1[k] * shO2W[k * 32 + jj];
        z2[jj] = sigm(s);
    }
    float z3[32];
#pragma unroll
    for (int jj = 0; jj < 32; jj++) {
        float s = shO3B[jj];
#pragma unroll
        for (int k = 0; k < 32; k++) s += z2[k] * shO3W[k * 32 + jj];
        z3[jj] = sigm(s);
    }
    float s = shO4B;
#pragma unroll
    for (int k = 0; k < 32; k++) s += z3[k] * shO4W[k];
    out[l] = sigm(s);
}

// ---------------------------------------------------------------------------
extern "C" void kernel_launch(void* const* d_in, const int* in_sizes, int n_in,
                              void* d_out, int out_size) {
    const float* x    = (const float*)d_in[0];
    const int*   src  = (const int*)  d_in[1];
    const int*   dst  = (const int*)  d_in[2];
    const int*   leaf = (const int*)  d_in[3];
    const float* cmd  = (const float*)d_in[4];
    const float* p1W  = (const float*)d_in[5];
    const float* p1b  = (const float*)d_in[6];
    const float* s1W  = (const float*)d_in[7];
    const float* n1W  = (const float*)d_in[8];
    const float* b1   = (const float*)d_in[9];
    const float* p2W  = (const float*)d_in[10];
    const float* p2b  = (const float*)d_in[11];
    const float* s2W  = (const float*)d_in[12];
    const float* n2W  = (const float*)d_in[13];
    const float* b2   = (const float*)d_in[14];
    const float* cmdW = (const float*)d_in[15];
    const float* cmdb = (const float*)d_in[16];
    const float* o1W  = (const float*)d_in[17];
    const float* o1b  = (const float*)d_in[18];
    const float* o2W  = (const float*)d_in[19];
    const float* o2b  = (const float*)d_in[20];
    const float* o3W  = (const float*)d_in[21];
    const float* o3b  = (const float*)d_in[22];
    const float* o4W  = (const float*)d_in[23];
    const float* o4b  = (const float*)d_in[24];
    float* out = (float*)d_out;

    int N = in_sizes[0] / 5;
    int E = in_sizes[1];
    int L = in_sizes[3];

    const int BT = 256;
    int nb = (N + BT - 1) / BT;
    int eb = (E + BT - 1) / BT;
    int lb = (L + BT - 1) / BT;
    int NB = (N + SCAN_CHUNK - 1) / SCAN_CHUNK;   // chunk count (<=1024)

    // Layer-1 pool fc + zero degrees
    k_pool1<<<nb, BT>>>(x, p1W, p1b, N);
    // Build dst-CSR (shared by both layers)
    k_hist        <<<eb, BT>>>(dst, E);
    k_scan_partial<<<NB, 1024>>>(N);
    k_scan_sums   <<<1, 1024>>>(NB);
    k_scan_add    <<<nb, BT>>>(N);
    k_scatter     <<<eb, BT>>>(src, dst, E);
    // Layer-1 aggregation + combine + layer-2 pool fc
    k_gather_mid<<<nb, BT>>>(x, s1W, n1W, b1, p2W, p2b, N);
    // Leaf-only layer-2 aggregation + combine + command + MLP
    k_leaf<<<lb, BT>>>(leaf, cmd, s2W, n2W, b2, cmdW, cmdb,
                       o1W, o1b, o2W, o2b, o3W, o3b, o4W, o4b, out, L);
}